// round 9
// baseline (speedup 1.0000x reference)
#include <cuda_runtime.h>
#include <cstdint>
#include <cstddef>

// ---------------------------------------------------------------------------
// JointSampling: gumbel-softmax (disc) + reparameterized gaussian (cont)
// JAX partitionable threefry2x32:
//   random_bits32(key, i) = x0 ^ x1 of threefry(key, (0, i))
//   split(key)[i]         = both output words of threefry(key, (0, i))
// Input : latent [B, 3072] f32
// Output: [ sample (B*2560) | mean (B*512) | logvar (B*512) ]  f32
// ---------------------------------------------------------------------------

#define N_CATEG 32
#define CATEG_N 64
#define DISC_LEN 2048
#define CONT_LEN 512
#define ROW_LEN 3072
#define SAMPLE_LEN 2560

static __device__ __forceinline__ uint32_t rotl32(uint32_t x, int r) {
    return __funnelshift_l(x, x, r);
}

// opaque-multiplier add: emits IMAD.LO (fma pipe) because `one` is a runtime reg
static __device__ __forceinline__ uint32_t madd(uint32_t a, uint32_t one, uint32_t c) {
    return a * one + c;
}

static __device__ __forceinline__ float frcp(float x) {
    float r;
    asm("rcp.approx.ftz.f32 %0, %1;" : "=f"(r) : "f"(x));
    return r;
}
static __device__ __forceinline__ float fex2(float x) {   // raw MUFU.EX2
    float r;
    asm("ex2.approx.ftz.f32 %0, %1;" : "=f"(r) : "f"(x));
    return r;
}
static __device__ __forceinline__ float flg2(float x) {   // raw MUFU.LG2
    float r;
    asm("lg2.approx.ftz.f32 %0, %1;" : "=f"(r) : "f"(x));
    return r;
}

// Host-side reference threefry (plain adds)
static __host__ void threefry2x32_host(uint32_t k0, uint32_t k1, uint32_t& x0, uint32_t& x1) {
    uint32_t ks2 = k0 ^ k1 ^ 0x1BD11BDAu;
    x0 += k0; x1 += k1;
#define TFH(r) { x0 += x1; x1 = (x1 << r) | (x1 >> (32 - r)); x1 ^= x0; }
    TFH(13) TFH(15) TFH(26) TFH(6)
    x0 += k1;  x1 += ks2 + 1u;
    TFH(17) TFH(29) TFH(16) TFH(24)
    x0 += ks2; x1 += k0 + 2u;
    TFH(13) TFH(15) TFH(26) TFH(6)
    x0 += k0;  x1 += k1 + 3u;
    TFH(17) TFH(29) TFH(16) TFH(24)
    x0 += k1;  x1 += ks2 + 4u;
    TFH(13) TFH(15) TFH(26) TFH(6)
    x0 += ks2; x1 += k0 + 5u;
#undef TFH
    // (final words)
}

// Device threefry, IADD3-fused key injections + IMAD-balanced round adds.
// Returns x0 ^ x1 for counter (0, i).
static __device__ __forceinline__ uint32_t tf_bits32(
    uint32_t k0, uint32_t k1, uint32_t ks2, uint32_t idx, uint32_t one) {
    // init + round 1 fused: x0 = (0+k0) + (idx+k1)
    uint32_t x1 = idx + k1;
    uint32_t x0 = x1 + k0;
    x1 = rotl32(x1, 13); x1 ^= x0;
#define TF_R(r) { x0 = madd(x1, one, x0); x1 = rotl32(x1, r); x1 ^= x0; }
#define TF_INJ(kx, c, r)  /* x1 += c; x0 += kx + x1 (IADD3); rot/xor */ \
    { x1 = x1 + (c); x0 = x0 + (kx) + x1; x1 = rotl32(x1, r); x1 ^= x0; }
    TF_R(15) TF_R(26) TF_R(6)
    TF_INJ(k1,  ks2 + 1u, 17)
    TF_R(29) TF_R(16) TF_R(24)
    TF_INJ(ks2, k0 + 2u,  13)
    TF_R(15) TF_R(26) TF_R(6)
    TF_INJ(k0,  k1 + 3u,  17)
    TF_R(29) TF_R(16) TF_R(24)
    TF_INJ(k1,  ks2 + 4u, 13)
    TF_R(15) TF_R(26) TF_R(6)
    x0 = madd(ks2, one, x0);
    x1 = madd(x1, one, k0 + 5u);
#undef TF_INJ
#undef TF_R
    return x0 ^ x1;
}

// bits -> [0,1): bitcast((bits>>9)|0x3f800000) - 1, built on the fma pipe
static __device__ __forceinline__ float bits_to_u01(uint32_t bits, uint32_t one) {
    uint32_t m = __umulhi(bits, 1u << 23);
    return __uint_as_float(madd(m, one, 0x3F800000u)) - 1.0f;
}

// bits -> [-1,1) directly: bitcast((bits>>9)|0x40000000) in [2,4), minus 3.
// Sterbenz-exact = 2*u01 - 1; differs from ref's 2*u01+nextafter(-1,0) by <=6e-8.
static __device__ __forceinline__ float bits_to_u11(uint32_t bits, uint32_t one) {
    uint32_t m = __umulhi(bits, 1u << 23);
    return __uint_as_float(madd(m, one, 0x40000000u)) - 3.0f;
}

// 4-step butterfly: reduces within each 16-lane half (both groups at once)
static __device__ __forceinline__ float half_warp_sum(float v) {
#pragma unroll
    for (int o = 8; o; o >>= 1) v += __shfl_xor_sync(0xffffffffu, v, o);
    return v;
}

// sqrt(2)*erfinv(x), Giles polynomial with sqrt2 pre-folded into coefficients
static __device__ __forceinline__ float sqrt2_erfinv_f32(float x) {
    float w = -__logf(fmaf(-x, x, 1.0f));
    float p;
    if (w < 5.0f) {
        w -= 2.5f;
        p = 3.97465172e-08f;
        p = fmaf(p, w, 4.85462093e-07f);
        p = fmaf(p, w, -4.98284884e-06f);
        p = fmaf(p, w, -6.21049041e-06f);
        p = fmaf(p, w, 3.09122935e-04f);
        p = fmaf(p, w, -1.77304094e-03f);
        p = fmaf(p, w, -5.90812175e-03f);
        p = fmaf(p, w, 3.48804458e-01f);
        p = fmaf(p, w, 2.12333113e+00f);
    } else {
        w = sqrtf(w) - 3.0f;
        p = -2.83145602e-04f;
        p = fmaf(p, w, 1.42765262e-04f);
        p = fmaf(p, w, 1.90826014e-03f);
        p = fmaf(p, w, -5.19503527e-03f);
        p = fmaf(p, w, 8.11697617e-03f);
        p = fmaf(p, w, -1.07800623e-02f);
        p = fmaf(p, w, 1.33486912e-02f);
        p = fmaf(p, w, 1.41658282e+00f);
        p = fmaf(p, w, 4.00648894e+00f);
    }
    return p * x;
}

// ---------------------------------------------------------------------------
// Fused kernel: blocks [0, n_disc_blocks) do disc, the rest do cont.
// Disc: one warp = 128 consecutive elements (two 64-wide groups in lane halves).
// Softmaxes without max-subtraction (inputs bounded; ratio identical to ~1ulp).
// ---------------------------------------------------------------------------
__global__ void __launch_bounds__(256)
fused_kernel(const float* __restrict__ latent, float* __restrict__ out,
             uint32_t kg0, uint32_t kg1, uint32_t kn0, uint32_t kn1,
             int n_disc_blocks, int n_pairs, int n_quads, int B, uint32_t one) {
    const float LOG2E  = 1.4426950408889634f;     // log2(e)
    const float NLN2   = -0.6931471805599453f;    // -ln(2)
    const float C2     = 2.8853900817779268f;     // 2*log2(e)  (tau = 0.5)
    const float NLN2C2 = NLN2 * C2;               // fold gumbel's -ln2 with C2

    if (blockIdx.x < (unsigned)n_disc_blocks) {
        // ------------------- disc -------------------
        int wg = blockIdx.x * 8 + (threadIdx.x >> 5);
        if (wg >= n_pairs) return;
        int lane = threadIdx.x & 31;
        uint32_t ks2 = kg0 ^ kg1 ^ 0x1BD11BDAu;

        int b  = wg >> 4;                 // / 16 chunks per row
        int gp = wg & 15;                 // 128-elem chunk within row

        const float4* rowp = (const float4*)(latent + (size_t)b * ROW_LEN + (size_t)gp * 128);
        float4 v = rowp[lane];

        // threefry noise: 4 consecutive counters per thread
        uint32_t base = ((uint32_t)wg << 7) + ((uint32_t)lane << 2);
        uint32_t b0 = tf_bits32(kg0, kg1, ks2, base,      one);
        uint32_t b1 = tf_bits32(kg0, kg1, ks2, base + 1u, one);
        uint32_t b2 = tf_bits32(kg0, kg1, ks2, base + 2u, one);
        uint32_t b3 = tf_bits32(kg0, kg1, ks2, base + 3u, one);

        // softmax #1 (no max-subtraction); one butterfly covers both lane-half groups
        float e0 = fex2(v.x * LOG2E), e1 = fex2(v.y * LOG2E);
        float e2 = fex2(v.z * LOG2E), e3 = fex2(v.w * LOG2E);
        float s = half_warp_sum((e0 + e1) + (e2 + e3));
        float rC2 = frcp(s) * C2;         // fold 1/s with tau scaling

        // gumbel, folded: gC2 = lg2( -ln2 * lg2(u) ) * (-ln2*C2)
        const float TINY = 1.17549435e-38f;
        float gc0 = flg2(flg2(fmaxf(TINY, bits_to_u01(b0, one))) * NLN2) * NLN2C2;
        float gc1 = flg2(flg2(fmaxf(TINY, bits_to_u01(b1, one))) * NLN2) * NLN2C2;
        float gc2 = flg2(flg2(fmaxf(TINY, bits_to_u01(b2, one))) * NLN2) * NLN2C2;
        float gc3 = flg2(flg2(fmaxf(TINY, bits_to_u01(b3, one))) * NLN2) * NLN2C2;

        // softmax #2: f = ex2( e*(r*C2) + g*C2 )
        float f0 = fex2(fmaf(e0, rC2, gc0));
        float f1 = fex2(fmaf(e1, rC2, gc1));
        float f2 = fex2(fmaf(e2, rC2, gc2));
        float f3 = fex2(fmaf(e3, rC2, gc3));
        float s2 = half_warp_sum((f0 + f1) + (f2 + f3));
        float r2 = frcp(s2);

        float4 o4 = make_float4(f0 * r2, f1 * r2, f2 * r2, f3 * r2);
        float4* orow = (float4*)(out + (size_t)b * SAMPLE_LEN + (size_t)gp * 128);
        orow[lane] = o4;
    } else {
        // ------------------- cont: 4 elements/thread, vectorized -------------
        int q = (blockIdx.x - n_disc_blocks) * 256 + threadIdx.x;
        if (q >= n_quads) return;
        uint32_t ks2 = kn0 ^ kn1 ^ 0x1BD11BDAu;

        int i = q * 4;          // first flat element
        int b = i >> 9;         // / CONT_LEN
        int j = i & 511;        // % CONT_LEN (multiple of 4)

        const float4* cptr = (const float4*)(latent + (size_t)b * ROW_LEN + DISC_LEN + (size_t)j * 2);
        float4 v0 = cptr[0];    // (m0, lv0, m1, lv1)
        float4 v1 = cptr[1];    // (m2, lv2, m3, lv3)

        uint32_t bits0 = tf_bits32(kn0, kn1, ks2, (uint32_t)i,      one);
        uint32_t bits1 = tf_bits32(kn0, kn1, ks2, (uint32_t)i + 1u, one);
        uint32_t bits2 = tf_bits32(kn0, kn1, ks2, (uint32_t)i + 2u, one);
        uint32_t bits3 = tf_bits32(kn0, kn1, ks2, (uint32_t)i + 3u, one);

        const float LO = -0.99999994f;      // nextafter(-1, 0): clamp (bits==0 -> -1)
        float u0 = fmaxf(LO, bits_to_u11(bits0, one));
        float u1 = fmaxf(LO, bits_to_u11(bits1, one));
        float u2 = fmaxf(LO, bits_to_u11(bits2, one));
        float u3 = fmaxf(LO, bits_to_u11(bits3, one));
        float e0 = sqrt2_erfinv_f32(u0);
        float e1 = sqrt2_erfinv_f32(u1);
        float e2 = sqrt2_erfinv_f32(u2);
        float e3 = sqrt2_erfinv_f32(u3);

        const float HLOG2E = 0.7213475204444817f;   // 0.5*log2(e)
        float4 cs;
        cs.x = fmaf(fex2(v0.y * HLOG2E), e0, v0.x);
        cs.y = fmaf(fex2(v0.w * HLOG2E), e1, v0.z);
        cs.z = fmaf(fex2(v1.y * HLOG2E), e2, v1.x);
        cs.w = fmaf(fex2(v1.w * HLOG2E), e3, v1.z);

        float4 mn = make_float4(v0.x, v0.z, v1.x, v1.z);
        float4 lv = make_float4(v0.y, v0.w, v1.y, v1.w);

        size_t sample_total = (size_t)B * SAMPLE_LEN;
        *(float4*)(out + (size_t)b * SAMPLE_LEN + DISC_LEN + j) = cs;
        *(float4*)(out + sample_total + (size_t)i) = mn;
        *(float4*)(out + sample_total + (size_t)B * CONT_LEN + (size_t)i) = lv;
    }
}

// ---------------------------------------------------------------------------
// Launch
// ---------------------------------------------------------------------------
extern "C" void kernel_launch(void* const* d_in, const int* in_sizes, int n_in,
                              void* d_out, int out_size) {
    const float* latent = (const float*)d_in[0];
    float* out = (float*)d_out;
    int B = in_sizes[0] / ROW_LEN;

    // Partitionable split of key(42) = (0, 42): subkey[i] = threefry((0,42), (0,i))
    uint32_t kg0 = 0u, kg1 = 0u;
    threefry2x32_host(0u, 42u, kg0, kg1);
    uint32_t kn0 = 0u, kn1 = 1u;
    threefry2x32_host(0u, 42u, kn0, kn1);

    uint32_t one = 1u;   // opaque multiplier (forces IMAD pipe balance)

    int n_pairs = B * (N_CATEG / 2);                     // 128-elem chunks (2 groups/warp)
    int n_disc_blocks = (n_pairs + 7) / 8;               // 8 warps per block
    int n_quads = (B * CONT_LEN) / 4;
    int n_cont_blocks = (n_quads + 255) / 256;

    fused_kernel<<<n_disc_blocks + n_cont_blocks, 256>>>(
        latent, out, kg0, kg1, kn0, kn1,
        n_disc_blocks, n_pairs, n_quads, B, one);
}

// round 12
// speedup vs baseline: 1.1345x; 1.1345x over previous
#include <cuda_runtime.h>
#include <cstdint>
#include <cstddef>

// ---------------------------------------------------------------------------
// JointSampling: gumbel-softmax (disc) + reparameterized gaussian (cont)
// JAX partitionable threefry2x32:
//   random_bits32(key, i) = x0 ^ x1 of threefry(key, (0, i))
//   split(key)[i]         = both output words of threefry(key, (0, i))
// Input : latent [B, 3072] f32
// Output: [ sample (B*2560) | mean (B*512) | logvar (B*512) ]  f32
// ---------------------------------------------------------------------------

#define N_CATEG 32
#define CATEG_N 64
#define DISC_LEN 2048
#define CONT_LEN 512
#define ROW_LEN 3072
#define SAMPLE_LEN 2560

static __device__ __forceinline__ uint32_t rotl32(uint32_t x, int r) {
    return __funnelshift_l(x, x, r);
}

// opaque-multiplier add: emits IMAD.LO (fma pipe) because `one` is a runtime reg
static __device__ __forceinline__ uint32_t madd(uint32_t a, uint32_t one, uint32_t c) {
    return a * one + c;
}

static __device__ __forceinline__ float frcp(float x) {
    float r;
    asm("rcp.approx.ftz.f32 %0, %1;" : "=f"(r) : "f"(x));
    return r;
}
static __device__ __forceinline__ float fex2(float x) {   // raw MUFU.EX2
    float r;
    asm("ex2.approx.ftz.f32 %0, %1;" : "=f"(r) : "f"(x));
    return r;
}
static __device__ __forceinline__ float flg2(float x) {   // raw MUFU.LG2
    float r;
    asm("lg2.approx.ftz.f32 %0, %1;" : "=f"(r) : "f"(x));
    return r;
}

// Host-side reference threefry (plain adds)
static __host__ void threefry2x32_host(uint32_t k0, uint32_t k1, uint32_t& x0, uint32_t& x1) {
    uint32_t ks2 = k0 ^ k1 ^ 0x1BD11BDAu;
    x0 += k0; x1 += k1;
#define TFH(r) { x0 += x1; x1 = (x1 << r) | (x1 >> (32 - r)); x1 ^= x0; }
    TFH(13) TFH(15) TFH(26) TFH(6)
    x0 += k1;  x1 += ks2 + 1u;
    TFH(17) TFH(29) TFH(16) TFH(24)
    x0 += ks2; x1 += k0 + 2u;
    TFH(13) TFH(15) TFH(26) TFH(6)
    x0 += k0;  x1 += k1 + 3u;
    TFH(17) TFH(29) TFH(16) TFH(24)
    x0 += k1;  x1 += ks2 + 4u;
    TFH(13) TFH(15) TFH(26) TFH(6)
    x0 += ks2; x1 += k0 + 5u;
#undef TFH
}

// Device threefry (R8 form: independent x0/x1 injections, IMAD-balanced adds).
// Returns x0 ^ x1 for counter (0, i).
static __device__ __forceinline__ uint32_t tf_bits32(
    uint32_t k0, uint32_t k1, uint32_t ks2, uint32_t idx, uint32_t one) {
    uint32_t x0 = k0;
    uint32_t x1 = madd(idx, one, k1);
#define TF_R(r) { x0 = madd(x1, one, x0); x1 = rotl32(x1, r); x1 ^= x0; }
    TF_R(13) TF_R(15) TF_R(26) TF_R(6)
    x0 = madd(k1, one, x0);  x1 = madd(x1, one, ks2 + 1u);
    TF_R(17) TF_R(29) TF_R(16) TF_R(24)
    x0 = madd(ks2, one, x0); x1 = madd(x1, one, k0 + 2u);
    TF_R(13) TF_R(15) TF_R(26) TF_R(6)
    x0 = madd(k0, one, x0);  x1 = madd(x1, one, k1 + 3u);
    TF_R(17) TF_R(29) TF_R(16) TF_R(24)
    x0 = madd(k1, one, x0);  x1 = madd(x1, one, ks2 + 4u);
    TF_R(13) TF_R(15) TF_R(26) TF_R(6)
    x0 = madd(ks2, one, x0); x1 = madd(x1, one, k0 + 5u);
#undef TF_R
    return x0 ^ x1;
}

// bits -> [0,1): bitcast((bits>>9)|0x3f800000) - 1, built on the fma pipe
static __device__ __forceinline__ float bits_to_u01(uint32_t bits, uint32_t one) {
    uint32_t m = __umulhi(bits, 1u << 23);
    return __uint_as_float(madd(m, one, 0x3F800000u)) - 1.0f;
}

// bits -> [-1,1): bitcast((bits>>9)|0x40000000) in [2,4), minus 3 (== 2*u01-1)
static __device__ __forceinline__ float bits_to_u11(uint32_t bits, uint32_t one) {
    uint32_t m = __umulhi(bits, 1u << 23);
    return __uint_as_float(madd(m, one, 0x40000000u)) - 3.0f;
}

// 4-step butterfly: reduces within each 16-lane half (two groups at once)
static __device__ __forceinline__ float half_warp_sum(float v) {
#pragma unroll
    for (int o = 8; o; o >>= 1) v += __shfl_xor_sync(0xffffffffu, v, o);
    return v;
}

// gumbel folded with tau: gc = lg2( -ln2 * lg2(u) ) * (-ln2 * 2*log2e)
// NOTE: no tiny-clamp. u==0 (P=2^-23) -> ex2(-inf)=0 downstream; the reference
// value there is ~1e-4 scaled by e^{-9} -- difference invisible at 1e-3 tol.
static __device__ __forceinline__ float gumbel_c2(uint32_t bits, uint32_t one) {
    const float NLN2   = -0.6931471805599453f;
    const float NLN2C2 = -0.6931471805599453f * 2.8853900817779268f;
    return flg2(flg2(bits_to_u01(bits, one)) * NLN2) * NLN2C2;
}

// sqrt(2)*erfinv(x), Giles polynomial with sqrt2 pre-folded into coefficients
static __device__ __forceinline__ float sqrt2_erfinv_f32(float x) {
    float w = -__logf(fmaf(-x, x, 1.0f));
    float p;
    if (w < 5.0f) {
        w -= 2.5f;
        p = 3.97465172e-08f;
        p = fmaf(p, w, 4.85462093e-07f);
        p = fmaf(p, w, -4.98284884e-06f);
        p = fmaf(p, w, -6.21049041e-06f);
        p = fmaf(p, w, 3.09122935e-04f);
        p = fmaf(p, w, -1.77304094e-03f);
        p = fmaf(p, w, -5.90812175e-03f);
        p = fmaf(p, w, 3.48804458e-01f);
        p = fmaf(p, w, 2.12333113e+00f);
    } else {
        w = sqrtf(w) - 3.0f;
        p = -2.83145602e-04f;
        p = fmaf(p, w, 1.42765262e-04f);
        p = fmaf(p, w, 1.90826014e-03f);
        p = fmaf(p, w, -5.19503527e-03f);
        p = fmaf(p, w, 8.11697617e-03f);
        p = fmaf(p, w, -1.07800623e-02f);
        p = fmaf(p, w, 1.33486912e-02f);
        p = fmaf(p, w, 1.41658282e+00f);
        p = fmaf(p, w, 4.00648894e+00f);
    }
    return p * x;
}

// ---------------------------------------------------------------------------
// Fused kernel: blocks [0, n_disc_blocks) do disc, the rest do cont.
// Disc: one warp = 256 consecutive elements (four 64-wide groups); thread t
// owns elements 4t..4t+3 and 128+4t..128+4t+3 (two float4s). Each 4-step
// half-warp butterfly reduces two groups at once (lane halves).
// Softmaxes without max-subtraction (inputs bounded; ratio identical to ~1ulp).
// ---------------------------------------------------------------------------
__global__ void __launch_bounds__(256)
fused_kernel(const float* __restrict__ latent, float* __restrict__ out,
             uint32_t kg0, uint32_t kg1, uint32_t kn0, uint32_t kn1,
             int n_disc_blocks, int n_chunks, int n_quads, int B, uint32_t one) {
    const float LOG2E = 1.4426950408889634f;     // log2(e)
    const float C2    = 2.8853900817779268f;     // 2*log2(e)  (tau = 0.5)

    if (blockIdx.x < (unsigned)n_disc_blocks) {
        // ------------------- disc -------------------
        int wg = blockIdx.x * 8 + (threadIdx.x >> 5);   // 256-elem chunk index
        if (wg >= n_chunks) return;
        int lane = threadIdx.x & 31;
        uint32_t ks2 = kg0 ^ kg1 ^ 0x1BD11BDAu;

        int b  = wg >> 3;                 // / 8 chunks per row
        int gp = wg & 7;                  // 256-elem chunk within row

        const float4* rowp = (const float4*)(latent + (size_t)b * ROW_LEN + (size_t)gp * 256);
        float4 va = rowp[lane];
        float4 vb = rowp[lane + 32];

        // threefry noise: 8 counters per thread (4 + 4, two 128-elem halves)
        uint32_t base = ((uint32_t)wg << 8) + ((uint32_t)lane << 2);
        uint32_t a0 = tf_bits32(kg0, kg1, ks2, base,        one);
        uint32_t a1 = tf_bits32(kg0, kg1, ks2, base + 1u,   one);
        uint32_t a2 = tf_bits32(kg0, kg1, ks2, base + 2u,   one);
        uint32_t a3 = tf_bits32(kg0, kg1, ks2, base + 3u,   one);
        uint32_t c0 = tf_bits32(kg0, kg1, ks2, base + 128u, one);
        uint32_t c1 = tf_bits32(kg0, kg1, ks2, base + 129u, one);
        uint32_t c2 = tf_bits32(kg0, kg1, ks2, base + 130u, one);
        uint32_t c3 = tf_bits32(kg0, kg1, ks2, base + 131u, one);

        // softmax #1 (no max-subtraction); butterflies reduce lane-half groups
        float ea0 = fex2(va.x * LOG2E), ea1 = fex2(va.y * LOG2E);
        float ea2 = fex2(va.z * LOG2E), ea3 = fex2(va.w * LOG2E);
        float eb0 = fex2(vb.x * LOG2E), eb1 = fex2(vb.y * LOG2E);
        float eb2 = fex2(vb.z * LOG2E), eb3 = fex2(vb.w * LOG2E);
        float sa = half_warp_sum((ea0 + ea1) + (ea2 + ea3));
        float sb = half_warp_sum((eb0 + eb1) + (eb2 + eb3));
        float raC2 = frcp(sa) * C2;
        float rbC2 = frcp(sb) * C2;

        float ga0 = gumbel_c2(a0, one), ga1 = gumbel_c2(a1, one);
        float ga2 = gumbel_c2(a2, one), ga3 = gumbel_c2(a3, one);
        float gb0 = gumbel_c2(c0, one), gb1 = gumbel_c2(c1, one);
        float gb2 = gumbel_c2(c2, one), gb3 = gumbel_c2(c3, one);

        // softmax #2: f = ex2( e*(r*C2) + g*C2 )
        float fa0 = fex2(fmaf(ea0, raC2, ga0));
        float fa1 = fex2(fmaf(ea1, raC2, ga1));
        float fa2 = fex2(fmaf(ea2, raC2, ga2));
        float fa3 = fex2(fmaf(ea3, raC2, ga3));
        float fb0 = fex2(fmaf(eb0, rbC2, gb0));
        float fb1 = fex2(fmaf(eb1, rbC2, gb1));
        float fb2 = fex2(fmaf(eb2, rbC2, gb2));
        float fb3 = fex2(fmaf(eb3, rbC2, gb3));
        float s2a = half_warp_sum((fa0 + fa1) + (fa2 + fa3));
        float s2b = half_warp_sum((fb0 + fb1) + (fb2 + fb3));
        float r2a = frcp(s2a);
        float r2b = frcp(s2b);

        float4* orow = (float4*)(out + (size_t)b * SAMPLE_LEN + (size_t)gp * 256);
        orow[lane]      = make_float4(fa0 * r2a, fa1 * r2a, fa2 * r2a, fa3 * r2a);
        orow[lane + 32] = make_float4(fb0 * r2b, fb1 * r2b, fb2 * r2b, fb3 * r2b);
    } else {
        // ------------------- cont: 4 elements/thread, vectorized -------------
        int q = (blockIdx.x - n_disc_blocks) * 256 + threadIdx.x;
        if (q >= n_quads) return;
        uint32_t ks2 = kn0 ^ kn1 ^ 0x1BD11BDAu;

        int i = q * 4;          // first flat element
        int b = i >> 9;         // / CONT_LEN
        int j = i & 511;        // % CONT_LEN (multiple of 4)

        const float4* cptr = (const float4*)(latent + (size_t)b * ROW_LEN + DISC_LEN + (size_t)j * 2);
        float4 v0 = cptr[0];    // (m0, lv0, m1, lv1)
        float4 v1 = cptr[1];    // (m2, lv2, m3, lv3)

        uint32_t bits0 = tf_bits32(kn0, kn1, ks2, (uint32_t)i,      one);
        uint32_t bits1 = tf_bits32(kn0, kn1, ks2, (uint32_t)i + 1u, one);
        uint32_t bits2 = tf_bits32(kn0, kn1, ks2, (uint32_t)i + 2u, one);
        uint32_t bits3 = tf_bits32(kn0, kn1, ks2, (uint32_t)i + 3u, one);

        const float LO = -0.99999994f;      // clamp: bits==0 would give exactly -1
        float u0 = fmaxf(LO, bits_to_u11(bits0, one));
        float u1 = fmaxf(LO, bits_to_u11(bits1, one));
        float u2 = fmaxf(LO, bits_to_u11(bits2, one));
        float u3 = fmaxf(LO, bits_to_u11(bits3, one));
        float e0 = sqrt2_erfinv_f32(u0);
        float e1 = sqrt2_erfinv_f32(u1);
        float e2 = sqrt2_erfinv_f32(u2);
        float e3 = sqrt2_erfinv_f32(u3);

        const float HLOG2E = 0.7213475204444817f;   // 0.5*log2(e)
        float4 cs;
        cs.x = fmaf(fex2(v0.y * HLOG2E), e0, v0.x);
        cs.y = fmaf(fex2(v0.w * HLOG2E), e1, v0.z);
        cs.z = fmaf(fex2(v1.y * HLOG2E), e2, v1.x);
        cs.w = fmaf(fex2(v1.w * HLOG2E), e3, v1.z);

        float4 mn = make_float4(v0.x, v0.z, v1.x, v1.z);
        float4 lv = make_float4(v0.y, v0.w, v1.y, v1.w);

        size_t sample_total = (size_t)B * SAMPLE_LEN;
        *(float4*)(out + (size_t)b * SAMPLE_LEN + DISC_LEN + j) = cs;
        *(float4*)(out + sample_total + (size_t)i) = mn;
        *(float4*)(out + sample_total + (size_t)B * CONT_LEN + (size_t)i) = lv;
    }
}

// ---------------------------------------------------------------------------
// Launch
// ---------------------------------------------------------------------------
extern "C" void kernel_launch(void* const* d_in, const int* in_sizes, int n_in,
                              void* d_out, int out_size) {
    const float* latent = (const float*)d_in[0];
    float* out = (float*)d_out;
    int B = in_sizes[0] / ROW_LEN;

    // Partitionable split of key(42) = (0, 42): subkey[i] = threefry((0,42), (0,i))
    uint32_t kg0 = 0u, kg1 = 0u;
    threefry2x32_host(0u, 42u, kg0, kg1);
    uint32_t kn0 = 0u, kn1 = 1u;
    threefry2x32_host(0u, 42u, kn0, kn1);

    uint32_t one = 1u;   // opaque multiplier (forces IMAD pipe balance)

    int n_chunks = B * (DISC_LEN / 256);                 // 256-elem chunks (4 groups/warp)
    int n_disc_blocks = (n_chunks + 7) / 8;              // 8 warps per block
    int n_quads = (B * CONT_LEN) / 4;
    int n_cont_blocks = (n_quads + 255) / 256;

    fused_kernel<<<n_disc_blocks + n_cont_blocks, 256>>>(
        latent, out, kg0, kg1, kn0, kn1,
        n_disc_blocks, n_chunks, n_quads, B, one);
}